// round 5
// baseline (speedup 1.0000x reference)
#include <cuda_runtime.h>
#include <cstdint>

#define BATCH 4096
#define RNK   64
#define DD    512

// ---------------- static device scratch ------------------------------------
__device__ uint32_t g_phiH[(size_t)BATCH * 1024];   // bf16-hi pairs, [b][cpair]
__device__ uint32_t g_phiL[(size_t)BATCH * 1024];   // bf16-lo pairs (r0 only)
__device__ uint32_t g_Bh1[32 * 4096 * 8];
__device__ uint32_t g_Bh2[32 * 4096 * 8];
__device__ uint32_t g_Bh3[32 * 2048 * 8];
__device__ float g_R0[BATCH * RNK];
__device__ float g_t1[BATCH * RNK];
__device__ float g_t2[BATCH * RNK];
__device__ float g_part[(size_t)32 * BATCH * RNK];

// ---------------- helpers ---------------------------------------------------
__device__ __forceinline__ uint32_t smem_u32(const void* p) {
    uint32_t a;
    asm("{ .reg .u64 t; cvta.to.shared.u64 t, %1; cvt.u32.u64 %0, t; }"
        : "=r"(a) : "l"(p));
    return a;
}
__device__ __forceinline__ uint32_t pack_bf16(float lo, float hi) {
    uint32_t r;
    asm("cvt.rn.bf16x2.f32 %0, %1, %2;" : "=r"(r) : "f"(hi), "f"(lo));
    return r;
}
__device__ __forceinline__ float bf16lo_f(uint32_t u) { return __uint_as_float(u << 16); }
__device__ __forceinline__ float bf16hi_f(uint32_t u) { return __uint_as_float(u & 0xFFFF0000u); }

#define CP_ASYNC16(dst, src) \
    asm volatile("cp.async.cg.shared.global [%0], [%1], 16;" :: "r"(dst), "l"(src) : "memory")
#define CP_COMMIT() asm volatile("cp.async.commit_group;" ::: "memory")
#define CP_WAIT(n)  asm volatile("cp.async.wait_group %0;" :: "n"(n) : "memory")

#define LDSM_X4(r0, r1, r2, r3, addr) \
    asm volatile("ldmatrix.sync.aligned.m8n8.x4.shared.b16 {%0,%1,%2,%3}, [%4];" \
        : "=r"(r0), "=r"(r1), "=r"(r2), "=r"(r3) : "r"(addr))

__device__ __forceinline__ void mma_bf16(float* c, const uint32_t* a, const uint32_t* b) {
    asm volatile(
        "mma.sync.aligned.m16n8k16.row.col.f32.bf16.bf16.f32 "
        "{%0,%1,%2,%3},{%4,%5,%6,%7},{%8,%9},{%0,%1,%2,%3};"
        : "+f"(c[0]), "+f"(c[1]), "+f"(c[2]), "+f"(c[3])
        : "r"(a[0]), "r"(a[1]), "r"(a[2]), "r"(a[3]), "r"(b[0]), "r"(b[1]));
}

// ---------------------------------------------------------------------------
// phi kernel: phi[b][c] = exp(-max(sq,0)*exp(-2 ls[c])) -> bf16 hi/lo planes
// ---------------------------------------------------------------------------
__global__ __launch_bounds__(256) void phi_kernel(const float* __restrict__ X,
                                                  const float* __restrict__ Cn,
                                                  const float* __restrict__ LS)
{
    __shared__ float XsT[32][64];
    __shared__ float CsT[32][64];
    __shared__ float xn[64], cn[64], sg[64];
    const int t  = threadIdx.x;
    const int c0 = blockIdx.x * 64;
    const int b0 = blockIdx.y * 64;

    for (int x = t; x < 64 * 32; x += 256) {
        int r = x >> 5, k = x & 31;
        XsT[k][r] = X[(b0 + r) * 32 + k];
        CsT[k][r] = Cn[(c0 + r) * 32 + k];
    }
    if (t < 64) sg[t] = __expf(-2.0f * LS[c0 + t]);
    __syncthreads();
    if (t < 64) {
        float s = 0.f;
        #pragma unroll
        for (int k = 0; k < 32; k++) { float v = XsT[k][t]; s += v * v; }
        xn[t] = s;
    } else if (t < 128) {
        int c = t - 64; float s = 0.f;
        #pragma unroll
        for (int k = 0; k < 32; k++) { float v = CsT[k][c]; s += v * v; }
        cn[c] = s;
    }
    __syncthreads();

    const int tc = (t & 15) * 4;
    const int tb = (t >> 4) * 4;
    float acc[4][4];
    #pragma unroll
    for (int i = 0; i < 4; i++)
        #pragma unroll
        for (int j = 0; j < 4; j++) acc[i][j] = 0.f;

    #pragma unroll
    for (int k = 0; k < 32; k++) {
        float4 xv = *reinterpret_cast<const float4*>(&XsT[k][tb]);
        float4 cv = *reinterpret_cast<const float4*>(&CsT[k][tc]);
        float xa[4] = {xv.x, xv.y, xv.z, xv.w};
        float ca[4] = {cv.x, cv.y, cv.z, cv.w};
        #pragma unroll
        for (int ci = 0; ci < 4; ci++)
            #pragma unroll
            for (int bi = 0; bi < 4; bi++)
                acc[ci][bi] += ca[ci] * xa[bi];
    }

    #pragma unroll
    for (int bi = 0; bi < 4; bi++) {
        float o[4];
        #pragma unroll
        for (int ci = 0; ci < 4; ci++) {
            float sq = fmaxf(xn[tb + bi] + cn[tc + ci] - 2.0f * acc[ci][bi], 0.0f);
            o[ci] = __expf(-sq * sg[tc + ci]);
        }
        uint32_t h01 = pack_bf16(o[0], o[1]);
        uint32_t h23 = pack_bf16(o[2], o[3]);
        uint32_t l01 = pack_bf16(o[0] - bf16lo_f(h01), o[1] - bf16hi_f(h01));
        uint32_t l23 = pack_bf16(o[2] - bf16lo_f(h23), o[3] - bf16hi_f(h23));
        size_t base = (size_t)(b0 + tb + bi) * 1024 + ((c0 + tc) >> 1);
        *reinterpret_cast<uint2*>(&g_phiH[base]) = make_uint2(h01, h23);
        *reinterpret_cast<uint2*>(&g_phiL[base]) = make_uint2(l01, l23);
    }
}

// ---------------------------------------------------------------------------
// Pack B (hi only): G[i][d][j] -> [kt][n][w] bf16 d-pairs, n = i*NOUT+j
// ---------------------------------------------------------------------------
template<int NOUT>
__global__ __launch_bounds__(256) void packB(const float* __restrict__ G,
                                             uint32_t* __restrict__ Bh)
{
    const int NB = NOUT * 64;
    int idx = blockIdx.x * 256 + threadIdx.x;
    int kt = blockIdx.y;
    int n = idx >> 3, w = idx & 7;
    int i = n / NOUT, j = n - i * NOUT;
    int d = kt * 16 + w * 2;
    float g0 = G[((size_t)i * DD + d) * NOUT + j];
    float g1 = G[((size_t)i * DD + d + 1) * NOUT + j];
    Bh[((size_t)kt * NB + n) * 8 + w] = pack_bf16(g0, g1);
}

// ---------------------------------------------------------------------------
// R0 = Phi0 @ G0 (FFMA, small)
// ---------------------------------------------------------------------------
__global__ __launch_bounds__(256) void r0_kernel(const float* __restrict__ G0)
{
    __shared__ float As[32][64];
    __shared__ float Bs[32][64];
    const int t  = threadIdx.x;
    const int b0 = blockIdx.x * 64;
    const int tb = (t & 15) * 4;
    const int tj = (t >> 4) * 4;
    float acc[4][4] = {};

    for (int d0 = 0; d0 < DD; d0 += 32) {
        __syncthreads();
        {
            int b = t >> 2, pq = t & 3;
            size_t base = (size_t)(b0 + b) * 1024 + (d0 >> 1) + pq * 4;
            uint4 h4 = *reinterpret_cast<const uint4*>(&g_phiH[base]);
            uint4 l4 = *reinterpret_cast<const uint4*>(&g_phiL[base]);
            uint32_t hh[4] = {h4.x, h4.y, h4.z, h4.w};
            uint32_t ll[4] = {l4.x, l4.y, l4.z, l4.w};
            #pragma unroll
            for (int q = 0; q < 4; q++) {
                As[pq * 8 + q * 2 + 0][b] = bf16lo_f(hh[q]) + bf16lo_f(ll[q]);
                As[pq * 8 + q * 2 + 1][b] = bf16hi_f(hh[q]) + bf16hi_f(ll[q]);
            }
        }
        for (int x = t; x < 32 * 64; x += 256) {
            int k = x >> 6, r = x & 63;
            Bs[k][r] = G0[(d0 + k) * RNK + r];
        }
        __syncthreads();
        #pragma unroll
        for (int k = 0; k < 32; k++) {
            float4 a = *reinterpret_cast<const float4*>(&As[k][tb]);
            float4 b = *reinterpret_cast<const float4*>(&Bs[k][tj]);
            float aa[4] = {a.x, a.y, a.z, a.w};
            float bb[4] = {b.x, b.y, b.z, b.w};
            #pragma unroll
            for (int bi = 0; bi < 4; bi++)
                #pragma unroll
                for (int ji = 0; ji < 4; ji++)
                    acc[bi][ji] += aa[bi] * bb[ji];
        }
    }
    #pragma unroll
    for (int bi = 0; bi < 4; bi++)
        #pragma unroll
        for (int ji = 0; ji < 4; ji++)
            g_R0[(b0 + tb + bi) * RNK + tj + ji] = acc[bi][ji];
}

// ---------------------------------------------------------------------------
// Stage GEMM (mma.sync bf16, single term Ah*Bh):
// H[b,(i,j)] = sum_d Phi[b,d] B[d,(i,j)]; epilogue folds V.
// Block 128m x 128n, 32 k16 steps, 8 warps (2m x 4n), ldmatrix fragment loads.
// SMEM: 4 bufs x (Ah | Bh), rows padded to 12 words.
// ---------------------------------------------------------------------------
template<int NOUT>
__global__ __launch_bounds__(256, 1) void stage_mma(const float* __restrict__ V,
                                                    const uint32_t* __restrict__ BhG,
                                                    int cpair0)
{
    const int NB = NOUT * 64;
    constexpr uint32_t BUFB = 3072u * 4u;      // bytes per pipeline buffer
    extern __shared__ uint32_t sm[];
    const uint32_t smb = smem_u32(sm);

    const int t    = threadIdx.x;
    const int lane = t & 31;
    const int wid  = t >> 5;
    const int wm   = wid >> 2;
    const int wn   = wid & 3;
    const int g    = lane >> 2;
    const int tg   = lane & 3;
    const int b0   = blockIdx.x * 128;
    const int nb0  = blockIdx.y * 128;

    const int row  = t >> 1;
    const int half = t & 1;

    const uint32_t* srcAh = g_phiH + (size_t)(b0 + row) * 1024 + cpair0 + half * 4;
    const uint32_t* srcBh = BhG + ((size_t)(nb0 + row)) * 8 + half * 4;
    const uint32_t dstA = smb + (row * 12 + half * 4) * 4;

    // ldmatrix per-lane offsets (bytes, within a buffer)
    const int rr  = lane & 7;
    const int sub = lane >> 3;
    const uint32_t aoff = (uint32_t)(((wm * 64 + rr + ((sub & 1) << 3)) * 12 +
                                      ((sub >> 1) << 2)) * 4);
    const uint32_t boff = (uint32_t)(((wn * 32 + ((sub >> 1) << 3) + rr) * 12 +
                                      ((sub & 1) << 2)) * 4);

    float acc[4][4][4];
    #pragma unroll
    for (int a = 0; a < 4; a++)
        #pragma unroll
        for (int b = 0; b < 4; b++)
            #pragma unroll
            for (int c = 0; c < 4; c++) acc[a][b][c] = 0.f;

    #pragma unroll
    for (int kt = 0; kt < 3; kt++) {
        uint32_t bb = (uint32_t)kt * BUFB;
        CP_ASYNC16(dstA + bb,        srcAh + kt * 8);
        CP_ASYNC16(dstA + bb + 6144, srcBh + (size_t)kt * NB * 8);
        CP_COMMIT();
    }

    for (int kt = 0; kt < 32; kt++) {
        if (kt < 30)       CP_WAIT(2);
        else if (kt == 30) CP_WAIT(1);
        else               CP_WAIT(0);
        __syncthreads();

        const uint32_t base = smb + (uint32_t)(kt & 3) * BUFB;

        uint32_t ah[4][4], bh[4][2];
        #pragma unroll
        for (int mf = 0; mf < 4; mf++)
            LDSM_X4(ah[mf][0], ah[mf][1], ah[mf][2], ah[mf][3], base + aoff + mf * 768u);
        LDSM_X4(bh[0][0], bh[0][1], bh[1][0], bh[1][1], base + 6144u + boff);
        LDSM_X4(bh[2][0], bh[2][1], bh[3][0], bh[3][1], base + 6144u + boff + 768u);

        #pragma unroll
        for (int mf = 0; mf < 4; mf++)
            #pragma unroll
            for (int nf = 0; nf < 4; nf++)
                mma_bf16(acc[mf][nf], ah[mf], bh[nf]);

        int kn = kt + 3;
        if (kn < 32) {
            uint32_t bb = (uint32_t)(kn & 3) * BUFB;
            CP_ASYNC16(dstA + bb,        srcAh + kn * 8);
            CP_ASYNC16(dstA + bb + 6144, srcBh + (size_t)kn * NB * 8);
            CP_COMMIT();
        }
    }
    __syncthreads();

    // ---- epilogue: scale by V[b,i], fold i within block, write partial ----
    float* red = reinterpret_cast<float*>(sm);
    constexpr int RP = (NOUT == 64) ? 72 : 36;

    const int iloc  = (NOUT == 64) ? (wn >> 1) : wn;
    const int iglob = blockIdx.y * (128 / NOUT) + iloc;
    const int jb    = (NOUT == 64) ? ((wn & 1) * 32) : 0;

    float vv[4][2];
    #pragma unroll
    for (int mf = 0; mf < 4; mf++) {
        int r = b0 + wm * 64 + mf * 16 + g;
        vv[mf][0] = V[(size_t)r * RNK + iglob];
        vv[mf][1] = V[(size_t)(r + 8) * RNK + iglob];
    }

    const int nphase = (NOUT == 64) ? 2 : 4;
    const int wpp    = (NOUT == 64) ? 2 : 1;
    #pragma unroll
    for (int ph = 0; ph < 4; ph++) {
        if (ph < nphase) {
            if (wn / wpp == ph) {
                #pragma unroll
                for (int mf = 0; mf < 4; mf++) {
                    int r = wm * 64 + mf * 16 + g;
                    #pragma unroll
                    for (int nf = 0; nf < 4; nf++) {
                        int j = jb + nf * 8 + tg * 2;
                        if (ph == 0) {
                            red[r * RP + j]           = acc[mf][nf][0] * vv[mf][0];
                            red[r * RP + j + 1]       = acc[mf][nf][1] * vv[mf][0];
                            red[(r + 8) * RP + j]     = acc[mf][nf][2] * vv[mf][1];
                            red[(r + 8) * RP + j + 1] = acc[mf][nf][3] * vv[mf][1];
                        } else {
                            red[r * RP + j]           += acc[mf][nf][0] * vv[mf][0];
                            red[r * RP + j + 1]       += acc[mf][nf][1] * vv[mf][0];
                            red[(r + 8) * RP + j]     += acc[mf][nf][2] * vv[mf][1];
                            red[(r + 8) * RP + j + 1] += acc[mf][nf][3] * vv[mf][1];
                        }
                    }
                }
            }
            __syncthreads();
        }
    }

    float* outp = g_part + (size_t)blockIdx.y * ((size_t)BATCH * NOUT);
    for (int x = t; x < 128 * NOUT; x += 256) {
        int r = x / NOUT, j = x % NOUT;
        outp[(size_t)(b0 + r) * NOUT + j] = red[r * RP + j];
    }
}

// ---------------------------------------------------------------------------
__global__ void combine_kernel(float* __restrict__ dst, int ng, int nout)
{
    int n = BATCH * nout;
    int x = blockIdx.x * blockDim.x + threadIdx.x;
    if (x < n) {
        float s = 0.f;
        for (int g = 0; g < ng; g++) s += g_part[(size_t)g * n + x];
        dst[x] = s;
    }
}

// ---------------------------------------------------------------------------
extern "C" void kernel_launch(void* const* d_in, const int* in_sizes, int n_in,
                              void* d_out, int out_size)
{
    const float* X  = (const float*)d_in[0];
    const float* Cn = (const float*)d_in[1];
    const float* LS = (const float*)d_in[2];
    const float* G0 = (const float*)d_in[3];
    const float* G1 = (const float*)d_in[4];
    const float* G2 = (const float*)d_in[5];
    const float* G3 = (const float*)d_in[6];
    float* out = (float*)d_out;

    void *pR0, *pT1, *pT2, *pBh1, *pBh2, *pBh3;
    cudaGetSymbolAddress(&pR0, g_R0);
    cudaGetSymbolAddress(&pT1, g_t1);
    cudaGetSymbolAddress(&pT2, g_t2);
    cudaGetSymbolAddress(&pBh1, g_Bh1);
    cudaGetSymbolAddress(&pBh2, g_Bh2);
    cudaGetSymbolAddress(&pBh3, g_Bh3);

    const int smemStage = 4 * 3072 * 4;   // 49152 B
    static int s_init = 0;
    if (!s_init) {
        cudaFuncSetAttribute(stage_mma<64>, cudaFuncAttributeMaxDynamicSharedMemorySize, smemStage);
        cudaFuncSetAttribute(stage_mma<32>, cudaFuncAttributeMaxDynamicSharedMemorySize, smemStage);
        s_init = 1;
    }

    phi_kernel<<<dim3(2048 / 64, BATCH / 64), 256>>>(X, Cn, LS);
    packB<64><<<dim3(4096 * 8 / 256, 32), 256>>>(G1, (uint32_t*)pBh1);
    packB<64><<<dim3(4096 * 8 / 256, 32), 256>>>(G2, (uint32_t*)pBh2);
    packB<32><<<dim3(2048 * 8 / 256, 32), 256>>>(G3, (uint32_t*)pBh3);
    r0_kernel<<<BATCH / 64, 256>>>(G0);

    stage_mma<64><<<dim3(BATCH / 128, 32), 256, smemStage>>>(
        (const float*)pR0, (const uint32_t*)pBh1, 256);
    combine_kernel<<<(BATCH * 64 + 255) / 256, 256>>>((float*)pT1, 32, 64);

    stage_mma<64><<<dim3(BATCH / 128, 32), 256, smemStage>>>(
        (const float*)pT1, (const uint32_t*)pBh2, 512);
    combine_kernel<<<(BATCH * 64 + 255) / 256, 256>>>((float*)pT2, 32, 64);

    stage_mma<32><<<dim3(BATCH / 128, 16), 256, smemStage>>>(
        (const float*)pT2, (const uint32_t*)pBh3, 768);
    combine_kernel<<<(BATCH * 32 + 255) / 256, 256>>>(out, 16, 32);
}

// round 6
// speedup vs baseline: 1.5035x; 1.5035x over previous
#include <cuda_runtime.h>
#include <cstdint>

#define BATCH 4096
#define RNK   64
#define DD    512

// ---------------- static device scratch ------------------------------------
__device__ uint32_t g_phiH[(size_t)BATCH * 1024];   // bf16-hi pairs, [b][cpair]
__device__ uint32_t g_phiL[(size_t)BATCH * 1024];   // bf16-lo pairs (r0 only)
__device__ uint32_t g_Bh1[32 * 4096 * 8];
__device__ uint32_t g_Bh2[32 * 4096 * 8];
__device__ uint32_t g_Bh3[32 * 2048 * 8];
__device__ float g_R0[BATCH * RNK];
__device__ float g_t1[BATCH * RNK];
__device__ float g_t2[BATCH * RNK];
__device__ float g_part[(size_t)32 * BATCH * RNK];

// ---------------- helpers ---------------------------------------------------
__device__ __forceinline__ uint32_t smem_u32(const void* p) {
    uint32_t a;
    asm("{ .reg .u64 t; cvta.to.shared.u64 t, %1; cvt.u32.u64 %0, t; }"
        : "=r"(a) : "l"(p));
    return a;
}
__device__ __forceinline__ uint32_t pack_bf16(float lo, float hi) {
    uint32_t r;
    asm("cvt.rn.bf16x2.f32 %0, %1, %2;" : "=r"(r) : "f"(hi), "f"(lo));
    return r;
}
__device__ __forceinline__ float bf16lo_f(uint32_t u) { return __uint_as_float(u << 16); }
__device__ __forceinline__ float bf16hi_f(uint32_t u) { return __uint_as_float(u & 0xFFFF0000u); }

// fast 2^t for t <= 0 (clamped), ~1e-8 relative accuracy, pure FMA pipe
__device__ __forceinline__ float fast_exp2(float t) {
    t = fmaxf(t, -126.0f);
    float i = rintf(t);
    float f = t - i;                       // f in [-0.5, 0.5]
    float p = 1.33988744e-3f;
    p = fmaf(p, f, 9.61843736e-3f);
    p = fmaf(p, f, 5.55033251e-2f);
    p = fmaf(p, f, 2.40226479e-1f);
    p = fmaf(p, f, 6.93147203e-1f);
    p = fmaf(p, f, 1.0f);
    return p * __uint_as_float((uint32_t)((int)i + 127) << 23);
}

#define CP_ASYNC16(dst, src) \
    asm volatile("cp.async.cg.shared.global [%0], [%1], 16;" :: "r"(dst), "l"(src) : "memory")
#define CP_COMMIT() asm volatile("cp.async.commit_group;" ::: "memory")
#define CP_WAIT(n)  asm volatile("cp.async.wait_group %0;" :: "n"(n) : "memory")

#define LDSM_X4(r0, r1, r2, r3, addr) \
    asm volatile("ldmatrix.sync.aligned.m8n8.x4.shared.b16 {%0,%1,%2,%3}, [%4];" \
        : "=r"(r0), "=r"(r1), "=r"(r2), "=r"(r3) : "r"(addr))

__device__ __forceinline__ void mma_bf16(float* c, const uint32_t* a, const uint32_t* b) {
    asm volatile(
        "mma.sync.aligned.m16n8k16.row.col.f32.bf16.bf16.f32 "
        "{%0,%1,%2,%3},{%4,%5,%6,%7},{%8,%9},{%0,%1,%2,%3};"
        : "+f"(c[0]), "+f"(c[1]), "+f"(c[2]), "+f"(c[3])
        : "r"(a[0]), "r"(a[1]), "r"(a[2]), "r"(a[3]), "r"(b[0]), "r"(b[1]));
}

// ---------------------------------------------------------------------------
// phi kernel: phi[b][c] = 2^(-max(sq,0)*exp(-2 ls[c])*log2e) -> bf16 hi/lo
// ---------------------------------------------------------------------------
__global__ __launch_bounds__(256) void phi_kernel(const float* __restrict__ X,
                                                  const float* __restrict__ Cn,
                                                  const float* __restrict__ LS)
{
    __shared__ float XsT[32][64];
    __shared__ float CsT[32][64];
    __shared__ float xn[64], cn[64], sg[64];
    const int t  = threadIdx.x;
    const int c0 = blockIdx.x * 64;
    const int b0 = blockIdx.y * 64;

    for (int x = t; x < 64 * 32; x += 256) {
        int r = x >> 5, k = x & 31;
        XsT[k][r] = X[(b0 + r) * 32 + k];
        CsT[k][r] = Cn[(c0 + r) * 32 + k];
    }
    if (t < 64) sg[t] = __expf(-2.0f * LS[c0 + t]) * 1.4426950408889634f;
    __syncthreads();
    if (t < 64) {
        float s = 0.f;
        #pragma unroll
        for (int k = 0; k < 32; k++) { float v = XsT[k][t]; s += v * v; }
        xn[t] = s;
    } else if (t < 128) {
        int c = t - 64; float s = 0.f;
        #pragma unroll
        for (int k = 0; k < 32; k++) { float v = CsT[k][c]; s += v * v; }
        cn[c] = s;
    }
    __syncthreads();

    const int tc = (t & 15) * 4;
    const int tb = (t >> 4) * 4;
    float acc[4][4];
    #pragma unroll
    for (int i = 0; i < 4; i++)
        #pragma unroll
        for (int j = 0; j < 4; j++) acc[i][j] = 0.f;

    #pragma unroll
    for (int k = 0; k < 32; k++) {
        float4 xv = *reinterpret_cast<const float4*>(&XsT[k][tb]);
        float4 cv = *reinterpret_cast<const float4*>(&CsT[k][tc]);
        float xa[4] = {xv.x, xv.y, xv.z, xv.w};
        float ca[4] = {cv.x, cv.y, cv.z, cv.w};
        #pragma unroll
        for (int ci = 0; ci < 4; ci++)
            #pragma unroll
            for (int bi = 0; bi < 4; bi++)
                acc[ci][bi] += ca[ci] * xa[bi];
    }

    #pragma unroll
    for (int bi = 0; bi < 4; bi++) {
        float o[4];
        #pragma unroll
        for (int ci = 0; ci < 4; ci++) {
            float sq = fmaxf(xn[tb + bi] + cn[tc + ci] - 2.0f * acc[ci][bi], 0.0f);
            o[ci] = fast_exp2(-sq * sg[tc + ci]);
        }
        uint32_t h01 = pack_bf16(o[0], o[1]);
        uint32_t h23 = pack_bf16(o[2], o[3]);
        uint32_t l01 = pack_bf16(o[0] - bf16lo_f(h01), o[1] - bf16hi_f(h01));
        uint32_t l23 = pack_bf16(o[2] - bf16lo_f(h23), o[3] - bf16hi_f(h23));
        size_t base = (size_t)(b0 + tb + bi) * 1024 + ((c0 + tc) >> 1);
        *reinterpret_cast<uint2*>(&g_phiH[base]) = make_uint2(h01, h23);
        *reinterpret_cast<uint2*>(&g_phiL[base]) = make_uint2(l01, l23);
    }
}

// ---------------------------------------------------------------------------
// Pack B (hi only): G[i][d][j] -> [kt][n][w] bf16 d-pairs, n = i*NOUT+j
// ---------------------------------------------------------------------------
template<int NOUT>
__global__ __launch_bounds__(256) void packB(const float* __restrict__ G,
                                             uint32_t* __restrict__ Bh)
{
    const int NB = NOUT * 64;
    int idx = blockIdx.x * 256 + threadIdx.x;
    int kt = blockIdx.y;
    int n = idx >> 3, w = idx & 7;
    int i = n / NOUT, j = n - i * NOUT;
    int d = kt * 16 + w * 2;
    float g0 = G[((size_t)i * DD + d) * NOUT + j];
    float g1 = G[((size_t)i * DD + d + 1) * NOUT + j];
    Bh[((size_t)kt * NB + n) * 8 + w] = pack_bf16(g0, g1);
}

// ---------------------------------------------------------------------------
// R0 = Phi0 @ G0 (FFMA, small)
// ---------------------------------------------------------------------------
__global__ __launch_bounds__(256) void r0_kernel(const float* __restrict__ G0)
{
    __shared__ float As[32][64];
    __shared__ float Bs[32][64];
    const int t  = threadIdx.x;
    const int b0 = blockIdx.x * 64;
    const int tb = (t & 15) * 4;
    const int tj = (t >> 4) * 4;
    float acc[4][4] = {};

    for (int d0 = 0; d0 < DD; d0 += 32) {
        __syncthreads();
        {
            int b = t >> 2, pq = t & 3;
            size_t base = (size_t)(b0 + b) * 1024 + (d0 >> 1) + pq * 4;
            uint4 h4 = *reinterpret_cast<const uint4*>(&g_phiH[base]);
            uint4 l4 = *reinterpret_cast<const uint4*>(&g_phiL[base]);
            uint32_t hh[4] = {h4.x, h4.y, h4.z, h4.w};
            uint32_t ll[4] = {l4.x, l4.y, l4.z, l4.w};
            #pragma unroll
            for (int q = 0; q < 4; q++) {
                As[pq * 8 + q * 2 + 0][b] = bf16lo_f(hh[q]) + bf16lo_f(ll[q]);
                As[pq * 8 + q * 2 + 1][b] = bf16hi_f(hh[q]) + bf16hi_f(ll[q]);
            }
        }
        for (int x = t; x < 32 * 64; x += 256) {
            int k = x >> 6, r = x & 63;
            Bs[k][r] = G0[(d0 + k) * RNK + r];
        }
        __syncthreads();
        #pragma unroll
        for (int k = 0; k < 32; k++) {
            float4 a = *reinterpret_cast<const float4*>(&As[k][tb]);
            float4 b = *reinterpret_cast<const float4*>(&Bs[k][tj]);
            float aa[4] = {a.x, a.y, a.z, a.w};
            float bb[4] = {b.x, b.y, b.z, b.w};
            #pragma unroll
            for (int bi = 0; bi < 4; bi++)
                #pragma unroll
                for (int ji = 0; ji < 4; ji++)
                    acc[bi][ji] += aa[bi] * bb[ji];
        }
    }
    #pragma unroll
    for (int bi = 0; bi < 4; bi++)
        #pragma unroll
        for (int ji = 0; ji < 4; ji++)
            g_R0[(b0 + tb + bi) * RNK + tj + ji] = acc[bi][ji];
}

// ---------------------------------------------------------------------------
// Stage GEMM (mma.sync bf16, single term):
// Chunked pipeline: 16 chunks of K=32 (2 k16 panels per chunk), 4 buffers.
// Buffer = [A panel0 | A panel1 | B panel0 | B panel1], each 128 rows x 12 words.
// One __syncthreads per chunk. 2 CTAs/SM via launch_bounds(256,2).
// ---------------------------------------------------------------------------
template<int NOUT>
__global__ __launch_bounds__(256, 2) void stage_mma(const float* __restrict__ V,
                                                    const uint32_t* __restrict__ BhG,
                                                    int cpair0)
{
    const int NB = NOUT * 64;
    constexpr uint32_t PAN  = 1536u * 4u;     // bytes per panel
    constexpr uint32_t BUFB = 4u * PAN;       // A0 A1 B0 B1
    extern __shared__ uint32_t sm[];
    const uint32_t smb = smem_u32(sm);

    const int t    = threadIdx.x;
    const int lane = t & 31;
    const int wid  = t >> 5;
    const int wm   = wid >> 2;
    const int wn   = wid & 3;
    const int g    = lane >> 2;
    const int tg   = lane & 3;
    const int b0   = blockIdx.x * 128;
    const int nb0  = blockIdx.y * 128;

    const int row  = t >> 1;
    const int half = t & 1;

    const uint32_t* srcAh = g_phiH + (size_t)(b0 + row) * 1024 + cpair0 + half * 4;
    const uint32_t* srcBh = BhG + ((size_t)(nb0 + row)) * 8 + half * 4;
    const uint32_t dstA = smb + (row * 12 + half * 4) * 4;

    const int rr  = lane & 7;
    const int sub = lane >> 3;
    const uint32_t aoff = (uint32_t)(((wm * 64 + rr + ((sub & 1) << 3)) * 12 +
                                      ((sub >> 1) << 2)) * 4);
    const uint32_t boff = (uint32_t)(((wn * 32 + ((sub >> 1) << 3) + rr) * 12 +
                                      ((sub & 1) << 2)) * 4);

    float acc[4][4][4];
    #pragma unroll
    for (int a = 0; a < 4; a++)
        #pragma unroll
        for (int b = 0; b < 4; b++)
            #pragma unroll
            for (int c = 0; c < 4; c++) acc[a][b][c] = 0.f;

    // prologue: chunks 0,1,2
    #pragma unroll
    for (int c = 0; c < 3; c++) {
        uint32_t bb = (uint32_t)c * BUFB;
        #pragma unroll
        for (int p = 0; p < 2; p++) {
            CP_ASYNC16(dstA + bb + p * PAN,           srcAh + (2 * c + p) * 8);
            CP_ASYNC16(dstA + bb + (2 + p) * PAN,     srcBh + (size_t)(2 * c + p) * NB * 8);
        }
        CP_COMMIT();
    }

    for (int c = 0; c < 16; c++) {
        if (c < 14)      CP_WAIT(2);
        else if (c == 14) CP_WAIT(1);
        else              CP_WAIT(0);
        __syncthreads();

        const uint32_t base = smb + (uint32_t)(c & 3) * BUFB;

        #pragma unroll
        for (int p = 0; p < 2; p++) {
            uint32_t ah[4][4], bh[4][2];
            const uint32_t pa = base + (uint32_t)p * PAN;
            const uint32_t pb = base + 2u * PAN + (uint32_t)p * PAN;
            #pragma unroll
            for (int mf = 0; mf < 4; mf++)
                LDSM_X4(ah[mf][0], ah[mf][1], ah[mf][2], ah[mf][3], pa + aoff + mf * 768u);
            LDSM_X4(bh[0][0], bh[0][1], bh[1][0], bh[1][1], pb + boff);
            LDSM_X4(bh[2][0], bh[2][1], bh[3][0], bh[3][1], pb + boff + 768u);

            #pragma unroll
            for (int mf = 0; mf < 4; mf++)
                #pragma unroll
                for (int nf = 0; nf < 4; nf++)
                    mma_bf16(acc[mf][nf], ah[mf], bh[nf]);
        }

        int cn = c + 3;
        if (cn < 16) {
            uint32_t bb = (uint32_t)(cn & 3) * BUFB;
            #pragma unroll
            for (int p = 0; p < 2; p++) {
                CP_ASYNC16(dstA + bb + p * PAN,       srcAh + (2 * cn + p) * 8);
                CP_ASYNC16(dstA + bb + (2 + p) * PAN, srcBh + (size_t)(2 * cn + p) * NB * 8);
            }
            CP_COMMIT();
        }
    }
    __syncthreads();

    // ---- epilogue: scale by V[b,i], fold i within block, write partial ----
    float* red = reinterpret_cast<float*>(sm);
    constexpr int RP = (NOUT == 64) ? 72 : 36;

    const int iloc  = (NOUT == 64) ? (wn >> 1) : wn;
    const int iglob = blockIdx.y * (128 / NOUT) + iloc;
    const int jb    = (NOUT == 64) ? ((wn & 1) * 32) : 0;

    float vv[4][2];
    #pragma unroll
    for (int mf = 0; mf < 4; mf++) {
        int r = b0 + wm * 64 + mf * 16 + g;
        vv[mf][0] = V[(size_t)r * RNK + iglob];
        vv[mf][1] = V[(size_t)(r + 8) * RNK + iglob];
    }

    const int nphase = (NOUT == 64) ? 2 : 4;
    const int wpp    = (NOUT == 64) ? 2 : 1;
    #pragma unroll
    for (int ph = 0; ph < 4; ph++) {
        if (ph < nphase) {
            if (wn / wpp == ph) {
                #pragma unroll
                for (int mf = 0; mf < 4; mf++) {
                    int r = wm * 64 + mf * 16 + g;
                    #pragma unroll
                    for (int nf = 0; nf < 4; nf++) {
                        int j = jb + nf * 8 + tg * 2;
                        if (ph == 0) {
                            red[r * RP + j]           = acc[mf][nf][0] * vv[mf][0];
                            red[r * RP + j + 1]       = acc[mf][nf][1] * vv[mf][0];
                            red[(r + 8) * RP + j]     = acc[mf][nf][2] * vv[mf][1];
                            red[(r + 8) * RP + j + 1] = acc[mf][nf][3] * vv[mf][1];
                        } else {
                            red[r * RP + j]           += acc[mf][nf][0] * vv[mf][0];
                            red[r * RP + j + 1]       += acc[mf][nf][1] * vv[mf][0];
                            red[(r + 8) * RP + j]     += acc[mf][nf][2] * vv[mf][1];
                            red[(r + 8) * RP + j + 1] += acc[mf][nf][3] * vv[mf][1];
                        }
                    }
                }
            }
            __syncthreads();
        }
    }

    float* outp = g_part + (size_t)blockIdx.y * ((size_t)BATCH * NOUT);
    for (int x = t; x < 128 * NOUT; x += 256) {
        int r = x / NOUT, j = x % NOUT;
        outp[(size_t)(b0 + r) * NOUT + j] = red[r * RP + j];
    }
}

// ---------------------------------------------------------------------------
__global__ void combine_kernel(float* __restrict__ dst, int ng, int nout)
{
    int n = BATCH * nout;
    int x = blockIdx.x * blockDim.x + threadIdx.x;
    if (x < n) {
        float s = 0.f;
        for (int g = 0; g < ng; g++) s += g_part[(size_t)g * n + x];
        dst[x] = s;
    }
}

// ---------------------------------------------------------------------------
extern "C" void kernel_launch(void* const* d_in, const int* in_sizes, int n_in,
                              void* d_out, int out_size)
{
    const float* X  = (const float*)d_in[0];
    const float* Cn = (const float*)d_in[1];
    const float* LS = (const float*)d_in[2];
    const float* G0 = (const float*)d_in[3];
    const float* G1 = (const float*)d_in[4];
    const float* G2 = (const float*)d_in[5];
    const float* G3 = (const float*)d_in[6];
    float* out = (float*)d_out;

    void *pR0, *pT1, *pT2, *pBh1, *pBh2, *pBh3;
    cudaGetSymbolAddress(&pR0, g_R0);
    cudaGetSymbolAddress(&pT1, g_t1);
    cudaGetSymbolAddress(&pT2, g_t2);
    cudaGetSymbolAddress(&pBh1, g_Bh1);
    cudaGetSymbolAddress(&pBh2, g_Bh2);
    cudaGetSymbolAddress(&pBh3, g_Bh3);

    const int smemStage = 4 * 6144 * 4;   // 98304 B (4 bufs x 24KB)
    static int s_init = 0;
    if (!s_init) {
        cudaFuncSetAttribute(stage_mma<64>, cudaFuncAttributeMaxDynamicSharedMemorySize, smemStage);
        cudaFuncSetAttribute(stage_mma<32>, cudaFuncAttributeMaxDynamicSharedMemorySize, smemStage);
        s_init = 1;
    }

    phi_kernel<<<dim3(2048 / 64, BATCH / 64), 256>>>(X, Cn, LS);
    packB<64><<<dim3(4096 * 8 / 256, 32), 256>>>(G1, (uint32_t*)pBh1);
    packB<64><<<dim3(4096 * 8 / 256, 32), 256>>>(G2, (uint32_t*)pBh2);
    packB<32><<<dim3(2048 * 8 / 256, 32), 256>>>(G3, (uint32_t*)pBh3);
    r0_kernel<<<BATCH / 64, 256>>>(G0);

    stage_mma<64><<<dim3(BATCH / 128, 32), 256, smemStage>>>(
        (const float*)pR0, (const uint32_t*)pBh1, 256);
    combine_kernel<<<(BATCH * 64 + 255) / 256, 256>>>((float*)pT1, 32, 64);

    stage_mma<64><<<dim3(BATCH / 128, 32), 256, smemStage>>>(
        (const float*)pT1, (const uint32_t*)pBh2, 512);
    combine_kernel<<<(BATCH * 64 + 255) / 256, 256>>>((float*)pT2, 32, 64);

    stage_mma<32><<<dim3(BATCH / 128, 16), 256, smemStage>>>(
        (const float*)pT2, (const uint32_t*)pBh3, 768);
    combine_kernel<<<(BATCH * 32 + 255) / 256, 256>>>(out, 16, 32);
}

// round 7
// speedup vs baseline: 1.5401x; 1.0244x over previous
#include <cuda_runtime.h>
#include <cstdint>

#define BATCH 4096
#define RNK   64
#define DD    512

// ---------------- static device scratch ------------------------------------
__device__ uint32_t g_phiH[(size_t)BATCH * 1024];   // bf16-hi pairs, [b][cpair]
__device__ uint32_t g_phiL[(size_t)BATCH * 1024];   // bf16-lo pairs (r0 only)
__device__ uint32_t g_Bh1[32 * 4096 * 8];
__device__ uint32_t g_Bh2[32 * 4096 * 8];
__device__ uint32_t g_Bh3[32 * 2048 * 8];
__device__ float g_R0[BATCH * RNK];
__device__ float g_t1[BATCH * RNK];
__device__ float g_t2[BATCH * RNK];
__device__ float g_part[(size_t)32 * BATCH * RNK];

// ---------------- helpers ---------------------------------------------------
__device__ __forceinline__ uint32_t smem_u32(const void* p) {
    uint32_t a;
    asm("{ .reg .u64 t; cvta.to.shared.u64 t, %1; cvt.u32.u64 %0, t; }"
        : "=r"(a) : "l"(p));
    return a;
}
__device__ __forceinline__ uint32_t pack_bf16(float lo, float hi) {
    uint32_t r;
    asm("cvt.rn.bf16x2.f32 %0, %1, %2;" : "=r"(r) : "f"(hi), "f"(lo));
    return r;
}
__device__ __forceinline__ float bf16lo_f(uint32_t u) { return __uint_as_float(u << 16); }
__device__ __forceinline__ float bf16hi_f(uint32_t u) { return __uint_as_float(u & 0xFFFF0000u); }

// fast 2^t for t <= 0 (clamped), ~1e-8 relative accuracy, pure FMA pipe
__device__ __forceinline__ float fast_exp2(float t) {
    t = fmaxf(t, -126.0f);
    float i = rintf(t);
    float f = t - i;                       // f in [-0.5, 0.5]
    float p = 1.33988744e-3f;
    p = fmaf(p, f, 9.61843736e-3f);
    p = fmaf(p, f, 5.55033251e-2f);
    p = fmaf(p, f, 2.40226479e-1f);
    p = fmaf(p, f, 6.93147203e-1f);
    p = fmaf(p, f, 1.0f);
    return p * __uint_as_float((uint32_t)((int)i + 127) << 23);
}

#define CP_ASYNC16(dst, src) \
    asm volatile("cp.async.cg.shared.global [%0], [%1], 16;" :: "r"(dst), "l"(src) : "memory")
#define CP_COMMIT() asm volatile("cp.async.commit_group;" ::: "memory")
#define CP_WAIT(n)  asm volatile("cp.async.wait_group %0;" :: "n"(n) : "memory")

#define LDSM_X4(r0, r1, r2, r3, addr) \
    asm volatile("ldmatrix.sync.aligned.m8n8.x4.shared.b16 {%0,%1,%2,%3}, [%4];" \
        : "=r"(r0), "=r"(r1), "=r"(r2), "=r"(r3) : "r"(addr))

__device__ __forceinline__ void mma_bf16(float* c, const uint32_t* a, const uint32_t* b) {
    asm volatile(
        "mma.sync.aligned.m16n8k16.row.col.f32.bf16.bf16.f32 "
        "{%0,%1,%2,%3},{%4,%5,%6,%7},{%8,%9},{%0,%1,%2,%3};"
        : "+f"(c[0]), "+f"(c[1]), "+f"(c[2]), "+f"(c[3])
        : "r"(a[0]), "r"(a[1]), "r"(a[2]), "r"(a[3]), "r"(b[0]), "r"(b[1]));
}

// ---------------------------------------------------------------------------
// phi kernel: phi[b][c] = 2^(-max(sq,0)*exp(-2 ls[c])*log2e) -> bf16 hi/lo
// ---------------------------------------------------------------------------
__global__ __launch_bounds__(256) void phi_kernel(const float* __restrict__ X,
                                                  const float* __restrict__ Cn,
                                                  const float* __restrict__ LS)
{
    __shared__ float XsT[32][64];
    __shared__ float CsT[32][64];
    __shared__ float xn[64], cn[64], sg[64];
    const int t  = threadIdx.x;
    const int c0 = blockIdx.x * 64;
    const int b0 = blockIdx.y * 64;

    for (int x = t; x < 64 * 32; x += 256) {
        int r = x >> 5, k = x & 31;
        XsT[k][r] = X[(b0 + r) * 32 + k];
        CsT[k][r] = Cn[(c0 + r) * 32 + k];
    }
    if (t < 64) sg[t] = __expf(-2.0f * LS[c0 + t]) * 1.4426950408889634f;
    __syncthreads();
    if (t < 64) {
        float s = 0.f;
        #pragma unroll
        for (int k = 0; k < 32; k++) { float v = XsT[k][t]; s += v * v; }
        xn[t] = s;
    } else if (t < 128) {
        int c = t - 64; float s = 0.f;
        #pragma unroll
        for (int k = 0; k < 32; k++) { float v = CsT[k][c]; s += v * v; }
        cn[c] = s;
    }
    __syncthreads();

    const int tc = (t & 15) * 4;
    const int tb = (t >> 4) * 4;
    float acc[4][4];
    #pragma unroll
    for (int i = 0; i < 4; i++)
        #pragma unroll
        for (int j = 0; j < 4; j++) acc[i][j] = 0.f;

    #pragma unroll
    for (int k = 0; k < 32; k++) {
        float4 xv = *reinterpret_cast<const float4*>(&XsT[k][tb]);
        float4 cv = *reinterpret_cast<const float4*>(&CsT[k][tc]);
        float xa[4] = {xv.x, xv.y, xv.z, xv.w};
        float ca[4] = {cv.x, cv.y, cv.z, cv.w};
        #pragma unroll
        for (int ci = 0; ci < 4; ci++)
            #pragma unroll
            for (int bi = 0; bi < 4; bi++)
                acc[ci][bi] += ca[ci] * xa[bi];
    }

    #pragma unroll
    for (int bi = 0; bi < 4; bi++) {
        float o[4];
        #pragma unroll
        for (int ci = 0; ci < 4; ci++) {
            float sq = fmaxf(xn[tb + bi] + cn[tc + ci] - 2.0f * acc[ci][bi], 0.0f);
            o[ci] = fast_exp2(-sq * sg[tc + ci]);
        }
        uint32_t h01 = pack_bf16(o[0], o[1]);
        uint32_t h23 = pack_bf16(o[2], o[3]);
        uint32_t l01 = pack_bf16(o[0] - bf16lo_f(h01), o[1] - bf16hi_f(h01));
        uint32_t l23 = pack_bf16(o[2] - bf16lo_f(h23), o[3] - bf16hi_f(h23));
        size_t base = (size_t)(b0 + tb + bi) * 1024 + ((c0 + tc) >> 1);
        *reinterpret_cast<uint2*>(&g_phiH[base]) = make_uint2(h01, h23);
        *reinterpret_cast<uint2*>(&g_phiL[base]) = make_uint2(l01, l23);
    }
}

// ---------------------------------------------------------------------------
// Pack B (merged): z=0 G1->Bh1 (N64), z=1 G2->Bh2 (N64), z=2 G3->Bh3 (N32)
// ---------------------------------------------------------------------------
__global__ __launch_bounds__(256) void packB_all(const float* __restrict__ G1,
                                                 const float* __restrict__ G2,
                                                 const float* __restrict__ G3,
                                                 uint32_t* __restrict__ Bh1,
                                                 uint32_t* __restrict__ Bh2,
                                                 uint32_t* __restrict__ Bh3)
{
    const int z = blockIdx.z;
    const int NOUT = (z == 2) ? 32 : 64;
    const int NB = NOUT * 64;
    const float* G = (z == 0) ? G1 : (z == 1) ? G2 : G3;
    uint32_t* Bh = (z == 0) ? Bh1 : (z == 1) ? Bh2 : Bh3;

    int idx = blockIdx.x * 256 + threadIdx.x;
    if (idx >= NB * 8) return;
    int kt = blockIdx.y;
    int n = idx >> 3, w = idx & 7;
    int i = n / NOUT, j = n - i * NOUT;
    int d = kt * 16 + w * 2;
    float g0 = G[((size_t)i * DD + d) * NOUT + j];
    float g1 = G[((size_t)i * DD + d + 1) * NOUT + j];
    Bh[((size_t)kt * NB + n) * 8 + w] = pack_bf16(g0, g1);
}

// ---------------------------------------------------------------------------
// R0 = Phi0 @ G0 (FFMA, split-K x4 -> g_part, combined later)
// ---------------------------------------------------------------------------
__global__ __launch_bounds__(256) void r0_kernel(const float* __restrict__ G0)
{
    __shared__ float As[32][64];
    __shared__ float Bs[32][64];
    const int t  = threadIdx.x;
    const int b0 = blockIdx.x * 64;
    const int dbase = blockIdx.y * 128;
    const int tb = (t & 15) * 4;
    const int tj = (t >> 4) * 4;
    float acc[4][4] = {};

    for (int d0 = dbase; d0 < dbase + 128; d0 += 32) {
        __syncthreads();
        {
            int b = t >> 2, pq = t & 3;
            size_t base = (size_t)(b0 + b) * 1024 + (d0 >> 1) + pq * 4;
            uint4 h4 = *reinterpret_cast<const uint4*>(&g_phiH[base]);
            uint4 l4 = *reinterpret_cast<const uint4*>(&g_phiL[base]);
            uint32_t hh[4] = {h4.x, h4.y, h4.z, h4.w};
            uint32_t ll[4] = {l4.x, l4.y, l4.z, l4.w};
            #pragma unroll
            for (int q = 0; q < 4; q++) {
                As[pq * 8 + q * 2 + 0][b] = bf16lo_f(hh[q]) + bf16lo_f(ll[q]);
                As[pq * 8 + q * 2 + 1][b] = bf16hi_f(hh[q]) + bf16hi_f(ll[q]);
            }
        }
        for (int x = t; x < 32 * 64; x += 256) {
            int k = x >> 6, r = x & 63;
            Bs[k][r] = G0[(d0 + k) * RNK + r];
        }
        __syncthreads();
        #pragma unroll
        for (int k = 0; k < 32; k++) {
            float4 a = *reinterpret_cast<const float4*>(&As[k][tb]);
            float4 b = *reinterpret_cast<const float4*>(&Bs[k][tj]);
            float aa[4] = {a.x, a.y, a.z, a.w};
            float bb[4] = {b.x, b.y, b.z, b.w};
            #pragma unroll
            for (int bi = 0; bi < 4; bi++)
                #pragma unroll
                for (int ji = 0; ji < 4; ji++)
                    acc[bi][ji] += aa[bi] * bb[ji];
        }
    }
    float* outp = g_part + (size_t)blockIdx.y * (BATCH * RNK);
    #pragma unroll
    for (int bi = 0; bi < 4; bi++)
        #pragma unroll
        for (int ji = 0; ji < 4; ji++)
            outp[(b0 + tb + bi) * RNK + tj + ji] = acc[bi][ji];
}

// ---------------------------------------------------------------------------
// Stage GEMM (mma.sync bf16, single term):
// 16 chunks of K=32 (2 k16 panels), 4 buffers, prefetch issued BEFORE compute.
// ---------------------------------------------------------------------------
template<int NOUT>
__global__ __launch_bounds__(256, 2) void stage_mma(const float* __restrict__ V,
                                                    const uint32_t* __restrict__ BhG,
                                                    int cpair0)
{
    const int NB = NOUT * 64;
    constexpr uint32_t PAN  = 1536u * 4u;     // bytes per panel
    constexpr uint32_t BUFB = 4u * PAN;       // A0 A1 B0 B1
    extern __shared__ uint32_t sm[];
    const uint32_t smb = smem_u32(sm);

    const int t    = threadIdx.x;
    const int lane = t & 31;
    const int wid  = t >> 5;
    const int wm   = wid >> 2;
    const int wn   = wid & 3;
    const int g    = lane >> 2;
    const int tg   = lane & 3;
    const int b0   = blockIdx.x * 128;
    const int nb0  = blockIdx.y * 128;

    const int row  = t >> 1;
    const int half = t & 1;

    const uint32_t* srcAh = g_phiH + (size_t)(b0 + row) * 1024 + cpair0 + half * 4;
    const uint32_t* srcBh = BhG + ((size_t)(nb0 + row)) * 8 + half * 4;
    const uint32_t dstA = smb + (row * 12 + half * 4) * 4;

    const int rr  = lane & 7;
    const int sub = lane >> 3;
    const uint32_t aoff = (uint32_t)(((wm * 64 + rr + ((sub & 1) << 3)) * 12 +
                                      ((sub >> 1) << 2)) * 4);
    const uint32_t boff = (uint32_t)(((wn * 32 + ((sub >> 1) << 3) + rr) * 12 +
                                      ((sub & 1) << 2)) * 4);

    float acc[4][4][4];
    #pragma unroll
    for (int a = 0; a < 4; a++)
        #pragma unroll
        for (int b = 0; b < 4; b++)
            #pragma unroll
            for (int c = 0; c < 4; c++) acc[a][b][c] = 0.f;

    // prologue: chunks 0,1,2
    #pragma unroll
    for (int c = 0; c < 3; c++) {
        uint32_t bb = (uint32_t)c * BUFB;
        #pragma unroll
        for (int p = 0; p < 2; p++) {
            CP_ASYNC16(dstA + bb + p * PAN,       srcAh + (2 * c + p) * 8);
            CP_ASYNC16(dstA + bb + (2 + p) * PAN, srcBh + (size_t)(2 * c + p) * NB * 8);
        }
        CP_COMMIT();
    }

    for (int c = 0; c < 16; c++) {
        if (c < 14)       CP_WAIT(2);
        else if (c == 14) CP_WAIT(1);
        else              CP_WAIT(0);
        __syncthreads();

        // prefetch chunk c+3 into buffer (c+3)&3 == (c-1)&3 (freed by this sync)
        int cn = c + 3;
        if (cn < 16) {
            uint32_t bb = (uint32_t)(cn & 3) * BUFB;
            #pragma unroll
            for (int p = 0; p < 2; p++) {
                CP_ASYNC16(dstA + bb + p * PAN,       srcAh + (2 * cn + p) * 8);
                CP_ASYNC16(dstA + bb + (2 + p) * PAN, srcBh + (size_t)(2 * cn + p) * NB * 8);
            }
            CP_COMMIT();
        }

        const uint32_t base = smb + (uint32_t)(c & 3) * BUFB;
        #pragma unroll
        for (int p = 0; p < 2; p++) {
            uint32_t ah[4][4], bh[4][2];
            const uint32_t pa = base + (uint32_t)p * PAN;
            const uint32_t pb = base + 2u * PAN + (uint32_t)p * PAN;
            #pragma unroll
            for (int mf = 0; mf < 4; mf++)
                LDSM_X4(ah[mf][0], ah[mf][1], ah[mf][2], ah[mf][3], pa + aoff + mf * 768u);
            LDSM_X4(bh[0][0], bh[0][1], bh[1][0], bh[1][1], pb + boff);
            LDSM_X4(bh[2][0], bh[2][1], bh[3][0], bh[3][1], pb + boff + 768u);

            #pragma unroll
            for (int mf = 0; mf < 4; mf++)
                #pragma unroll
                for (int nf = 0; nf < 4; nf++)
                    mma_bf16(acc[mf][nf], ah[mf], bh[nf]);
        }
    }
    __syncthreads();

    // ---- epilogue: scale by V[b,i], fold i within block, write partial ----
    float* red = reinterpret_cast<float*>(sm);
    constexpr int RP = (NOUT == 64) ? 72 : 36;

    const int iloc  = (NOUT == 64) ? (wn >> 1) : wn;
    const int iglob = blockIdx.y * (128 / NOUT) + iloc;
    const int jb    = (NOUT == 64) ? ((wn & 1) * 32) : 0;

    float vv[4][2];
    #pragma unroll
    for (int mf = 0; mf < 4; mf++) {
        int r = b0 + wm * 64 + mf * 16 + g;
        vv[mf][0] = V[(size_t)r * RNK + iglob];
        vv[mf][1] = V[(size_t)(r + 8) * RNK + iglob];
    }

    const int nphase = (NOUT == 64) ? 2 : 4;
    const int wpp    = (NOUT == 64) ? 2 : 1;
    #pragma unroll
    for (int ph = 0; ph < 4; ph++) {
        if (ph < nphase) {
            if (wn / wpp == ph) {
                #pragma unroll
                for (int mf = 0; mf < 4; mf++) {
                    int r = wm * 64 + mf * 16 + g;
                    #pragma unroll
                    for (int nf = 0; nf < 4; nf++) {
                        int j = jb + nf * 8 + tg * 2;
                        if (ph == 0) {
                            red[r * RP + j]           = acc[mf][nf][0] * vv[mf][0];
                            red[r * RP + j + 1]       = acc[mf][nf][1] * vv[mf][0];
                            red[(r + 8) * RP + j]     = acc[mf][nf][2] * vv[mf][1];
                            red[(r + 8) * RP + j + 1] = acc[mf][nf][3] * vv[mf][1];
                        } else {
                            red[r * RP + j]           += acc[mf][nf][0] * vv[mf][0];
                            red[r * RP + j + 1]       += acc[mf][nf][1] * vv[mf][0];
                            red[(r + 8) * RP + j]     += acc[mf][nf][2] * vv[mf][1];
                            red[(r + 8) * RP + j + 1] += acc[mf][nf][3] * vv[mf][1];
                        }
                    }
                }
            }
            __syncthreads();
        }
    }

    float* outp = g_part + (size_t)blockIdx.y * ((size_t)BATCH * NOUT);
    for (int x = t; x < 128 * NOUT; x += 256) {
        int r = x / NOUT, j = x % NOUT;
        outp[(size_t)(b0 + r) * NOUT + j] = red[r * RP + j];
    }
}

// ---------------------------------------------------------------------------
// combine: dst[x] = sum_g part[g][x], vectorized float4
// ---------------------------------------------------------------------------
__global__ void combine_kernel(float* __restrict__ dst, int ng, int nout)
{
    int n4 = BATCH * nout / 4;
    int x = blockIdx.x * blockDim.x + threadIdx.x;
    if (x < n4) {
        const float4* p = reinterpret_cast<const float4*>(g_part);
        float4 s = p[x];
        for (int g = 1; g < ng; g++) {
            float4 v = p[(size_t)g * n4 + x];
            s.x += v.x; s.y += v.y; s.z += v.z; s.w += v.w;
        }
        reinterpret_cast<float4*>(dst)[x] = s;
    }
}

// ---------------------------------------------------------------------------
extern "C" void kernel_launch(void* const* d_in, const int* in_sizes, int n_in,
                              void* d_out, int out_size)
{
    const float* X  = (const float*)d_in[0];
    const float* Cn = (const float*)d_in[1];
    const float* LS = (const float*)d_in[2];
    const float* G0 = (const float*)d_in[3];
    const float* G1 = (const float*)d_in[4];
    const float* G2 = (const float*)d_in[5];
    const float* G3 = (const float*)d_in[6];
    float* out = (float*)d_out;

    void *pR0, *pT1, *pT2, *pBh1, *pBh2, *pBh3;
    cudaGetSymbolAddress(&pR0, g_R0);
    cudaGetSymbolAddress(&pT1, g_t1);
    cudaGetSymbolAddress(&pT2, g_t2);
    cudaGetSymbolAddress(&pBh1, g_Bh1);
    cudaGetSymbolAddress(&pBh2, g_Bh2);
    cudaGetSymbolAddress(&pBh3, g_Bh3);

    const int smemStage = 4 * 6144 * 4;   // 98304 B (4 bufs x 24KB)
    static int s_init = 0;
    if (!s_init) {
        cudaFuncSetAttribute(stage_mma<64>, cudaFuncAttributeMaxDynamicSharedMemorySize, smemStage);
        cudaFuncSetAttribute(stage_mma<32>, cudaFuncAttributeMaxDynamicSharedMemorySize, smemStage);
        s_init = 1;
    }

    phi_kernel<<<dim3(2048 / 64, BATCH / 64), 256>>>(X, Cn, LS);
    packB_all<<<dim3(128, 32, 3), 256>>>(G1, G2, G3,
        (uint32_t*)pBh1, (uint32_t*)pBh2, (uint32_t*)pBh3);

    r0_kernel<<<dim3(BATCH / 64, 4), 256>>>(G0);
    combine_kernel<<<(BATCH * 64 / 4 + 255) / 256, 256>>>((float*)pR0, 4, 64);

    stage_mma<64><<<dim3(BATCH / 128, 32), 256, smemStage>>>(
        (const float*)pR0, (const uint32_t*)pBh1, 256);
    combine_kernel<<<(BATCH * 64 / 4 + 255) / 256, 256>>>((float*)pT1, 32, 64);

    stage_mma<64><<<dim3(BATCH / 128, 32), 256, smemStage>>>(
        (const float*)pT1, (const uint32_t*)pBh2, 512);
    combine_kernel<<<(BATCH * 64 / 4 + 255) / 256, 256>>>((float*)pT2, 32, 64);

    stage_mma<32><<<dim3(BATCH / 128, 16), 256, smemStage>>>(
        (const float*)pT2, (const uint32_t*)pBh3, 768);
    combine_kernel<<<(BATCH * 32 / 4 + 255) / 256, 256>>>(out, 16, 32);
}

// round 8
// speedup vs baseline: 1.6040x; 1.0415x over previous
#include <cuda_runtime.h>
#include <cstdint>

#define BATCH 4096
#define RNK   64
#define DD    512

// ---------------- static device scratch ------------------------------------
__device__ uint32_t g_phiH[(size_t)BATCH * 1024];   // bf16-hi pairs, [b][cpair]
__device__ uint32_t g_phiL[(size_t)BATCH * 1024];   // bf16-lo pairs (r0 only)
__device__ uint32_t g_Bh1[32 * 4096 * 8];
__device__ uint32_t g_Bh2[32 * 4096 * 8];
__device__ uint32_t g_Bh3[32 * 2048 * 8];
__device__ float g_R0[BATCH * RNK];
__device__ float g_t1[BATCH * RNK];
__device__ float g_t2[BATCH * RNK];
__device__ float g_part[(size_t)4 * BATCH * RNK];   // r0 split-K partials only

// ---------------- helpers ---------------------------------------------------
__device__ __forceinline__ uint32_t smem_u32(const void* p) {
    uint32_t a;
    asm("{ .reg .u64 t; cvta.to.shared.u64 t, %1; cvt.u32.u64 %0, t; }"
        : "=r"(a) : "l"(p));
    return a;
}
__device__ __forceinline__ uint32_t pack_bf16(float lo, float hi) {
    uint32_t r;
    asm("cvt.rn.bf16x2.f32 %0, %1, %2;" : "=r"(r) : "f"(hi), "f"(lo));
    return r;
}
__device__ __forceinline__ float bf16lo_f(uint32_t u) { return __uint_as_float(u << 16); }
__device__ __forceinline__ float bf16hi_f(uint32_t u) { return __uint_as_float(u & 0xFFFF0000u); }

// fast 2^t for t <= 0 (clamped), ~1e-8 relative accuracy, pure FMA pipe
__device__ __forceinline__ float fast_exp2(float t) {
    t = fmaxf(t, -126.0f);
    float i = rintf(t);
    float f = t - i;                       // f in [-0.5, 0.5]
    float p = 1.33988744e-3f;
    p = fmaf(p, f, 9.61843736e-3f);
    p = fmaf(p, f, 5.55033251e-2f);
    p = fmaf(p, f, 2.40226479e-1f);
    p = fmaf(p, f, 6.93147203e-1f);
    p = fmaf(p, f, 1.0f);
    return p * __uint_as_float((uint32_t)((int)i + 127) << 23);
}

#define CP_ASYNC16(dst, src) \
    asm volatile("cp.async.cg.shared.global [%0], [%1], 16;" :: "r"(dst), "l"(src) : "memory")
#define CP_COMMIT() asm volatile("cp.async.commit_group;" ::: "memory")
#define CP_WAIT(n)  asm volatile("cp.async.wait_group %0;" :: "n"(n) : "memory")

#define LDSM_X4(r0, r1, r2, r3, addr) \
    asm volatile("ldmatrix.sync.aligned.m8n8.x4.shared.b16 {%0,%1,%2,%3}, [%4];" \
        : "=r"(r0), "=r"(r1), "=r"(r2), "=r"(r3) : "r"(addr))

__device__ __forceinline__ void mma_bf16(float* c, const uint32_t* a, const uint32_t* b) {
    asm volatile(
        "mma.sync.aligned.m16n8k16.row.col.f32.bf16.bf16.f32 "
        "{%0,%1,%2,%3},{%4,%5,%6,%7},{%8,%9},{%0,%1,%2,%3};"
        : "+f"(c[0]), "+f"(c[1]), "+f"(c[2]), "+f"(c[3])
        : "r"(a[0]), "r"(a[1]), "r"(a[2]), "r"(a[3]), "r"(b[0]), "r"(b[1]));
}

// ---------------------------------------------------------------------------
// phi kernel: phi[b][c] = 2^(-max(sq,0)*exp(-2 ls[c])*log2e) -> bf16 hi/lo
// ---------------------------------------------------------------------------
__global__ __launch_bounds__(256) void phi_kernel(const float* __restrict__ X,
                                                  const float* __restrict__ Cn,
                                                  const float* __restrict__ LS)
{
    __shared__ float XsT[32][64];
    __shared__ float CsT[32][64];
    __shared__ float xn[64], cn[64], sg[64];
    const int t  = threadIdx.x;
    const int c0 = blockIdx.x * 64;
    const int b0 = blockIdx.y * 64;

    for (int x = t; x < 64 * 32; x += 256) {
        int r = x >> 5, k = x & 31;
        XsT[k][r] = X[(b0 + r) * 32 + k];
        CsT[k][r] = Cn[(c0 + r) * 32 + k];
    }
    if (t < 64) sg[t] = __expf(-2.0f * LS[c0 + t]) * 1.4426950408889634f;
    __syncthreads();
    if (t < 64) {
        float s = 0.f;
        #pragma unroll
        for (int k = 0; k < 32; k++) { float v = XsT[k][t]; s += v * v; }
        xn[t] = s;
    } else if (t < 128) {
        int c = t - 64; float s = 0.f;
        #pragma unroll
        for (int k = 0; k < 32; k++) { float v = CsT[k][c]; s += v * v; }
        cn[c] = s;
    }
    __syncthreads();

    const int tc = (t & 15) * 4;
    const int tb = (t >> 4) * 4;
    float acc[4][4];
    #pragma unroll
    for (int i = 0; i < 4; i++)
        #pragma unroll
        for (int j = 0; j < 4; j++) acc[i][j] = 0.f;

    #pragma unroll
    for (int k = 0; k < 32; k++) {
        float4 xv = *reinterpret_cast<const float4*>(&XsT[k][tb]);
        float4 cv = *reinterpret_cast<const float4*>(&CsT[k][tc]);
        float xa[4] = {xv.x, xv.y, xv.z, xv.w};
        float ca[4] = {cv.x, cv.y, cv.z, cv.w};
        #pragma unroll
        for (int ci = 0; ci < 4; ci++)
            #pragma unroll
            for (int bi = 0; bi < 4; bi++)
                acc[ci][bi] += ca[ci] * xa[bi];
    }

    #pragma unroll
    for (int bi = 0; bi < 4; bi++) {
        float o[4];
        #pragma unroll
        for (int ci = 0; ci < 4; ci++) {
            float sq = fmaxf(xn[tb + bi] + cn[tc + ci] - 2.0f * acc[ci][bi], 0.0f);
            o[ci] = fast_exp2(-sq * sg[tc + ci]);
        }
        uint32_t h01 = pack_bf16(o[0], o[1]);
        uint32_t h23 = pack_bf16(o[2], o[3]);
        uint32_t l01 = pack_bf16(o[0] - bf16lo_f(h01), o[1] - bf16hi_f(h01));
        uint32_t l23 = pack_bf16(o[2] - bf16lo_f(h23), o[3] - bf16hi_f(h23));
        size_t base = (size_t)(b0 + tb + bi) * 1024 + ((c0 + tc) >> 1);
        *reinterpret_cast<uint2*>(&g_phiH[base]) = make_uint2(h01, h23);
        *reinterpret_cast<uint2*>(&g_phiL[base]) = make_uint2(l01, l23);
    }
}

// ---------------------------------------------------------------------------
// Pack B (merged, j-major): n = j*64 + i.  z=0 G1, z=1 G2, z=2 G3(NOUT=32)
// ---------------------------------------------------------------------------
__global__ __launch_bounds__(256) void packB_all(const float* __restrict__ G1,
                                                 const float* __restrict__ G2,
                                                 const float* __restrict__ G3,
                                                 uint32_t* __restrict__ Bh1,
                                                 uint32_t* __restrict__ Bh2,
                                                 uint32_t* __restrict__ Bh3)
{
    const int z = blockIdx.z;
    const int NOUT = (z == 2) ? 32 : 64;
    const int NB = NOUT * 64;
    const float* G = (z == 0) ? G1 : (z == 1) ? G2 : G3;
    uint32_t* Bh = (z == 0) ? Bh1 : (z == 1) ? Bh2 : Bh3;

    int idx = blockIdx.x * 256 + threadIdx.x;
    if (idx >= NB * 8) return;
    int kt = blockIdx.y;
    int n = idx >> 3, w = idx & 7;
    int j = n >> 6, i = n & 63;          // j-major ordering
    int d = kt * 16 + w * 2;
    float g0 = G[((size_t)i * DD + d) * NOUT + j];
    float g1 = G[((size_t)i * DD + d + 1) * NOUT + j];
    Bh[((size_t)kt * NB + n) * 8 + w] = pack_bf16(g0, g1);
}

// ---------------------------------------------------------------------------
// R0 = Phi0 @ G0 (FFMA, split-K x4 -> g_part, combined later)
// ---------------------------------------------------------------------------
__global__ __launch_bounds__(256) void r0_kernel(const float* __restrict__ G0)
{
    __shared__ float As[32][64];
    __shared__ float Bs[32][64];
    const int t  = threadIdx.x;
    const int b0 = blockIdx.x * 64;
    const int dbase = blockIdx.y * 128;
    const int tb = (t & 15) * 4;
    const int tj = (t >> 4) * 4;
    float acc[4][4] = {};

    for (int d0 = dbase; d0 < dbase + 128; d0 += 32) {
        __syncthreads();
        {
            int b = t >> 2, pq = t & 3;
            size_t base = (size_t)(b0 + b) * 1024 + (d0 >> 1) + pq * 4;
            uint4 h4 = *reinterpret_cast<const uint4*>(&g_phiH[base]);
            uint4 l4 = *reinterpret_cast<const uint4*>(&g_phiL[base]);
            uint32_t hh[4] = {h4.x, h4.y, h4.z, h4.w};
            uint32_t ll[4] = {l4.x, l4.y, l4.z, l4.w};
            #pragma unroll
            for (int q = 0; q < 4; q++) {
                As[pq * 8 + q * 2 + 0][b] = bf16lo_f(hh[q]) + bf16lo_f(ll[q]);
                As[pq * 8 + q * 2 + 1][b] = bf16hi_f(hh[q]) + bf16hi_f(ll[q]);
            }
        }
        for (int x = t; x < 32 * 64; x += 256) {
            int k = x >> 6, r = x & 63;
            Bs[k][r] = G0[(d0 + k) * RNK + r];
        }
        __syncthreads();
        #pragma unroll
        for (int k = 0; k < 32; k++) {
            float4 a = *reinterpret_cast<const float4*>(&As[k][tb]);
            float4 b = *reinterpret_cast<const float4*>(&Bs[k][tj]);
            float aa[4] = {a.x, a.y, a.z, a.w};
            float bb[4] = {b.x, b.y, b.z, b.w};
            #pragma unroll
            for (int bi = 0; bi < 4; bi++)
                #pragma unroll
                for (int ji = 0; ji < 4; ji++)
                    acc[bi][ji] += aa[bi] * bb[ji];
        }
    }
    float* outp = g_part + (size_t)blockIdx.y * (BATCH * RNK);
    #pragma unroll
    for (int bi = 0; bi < 4; bi++)
        #pragma unroll
        for (int ji = 0; ji < 4; ji++)
            outp[(b0 + tb + bi) * RNK + tj + ji] = acc[bi][ji];
}

// ---------------------------------------------------------------------------
// Stage GEMM (mma.sync bf16, j-major B): block covers 2 j x all 64 i.
// Epilogue: fold V over i fully in-block (shfl + smem), write 2 final columns.
// NJTOT = output width (64 for t1/t2, 32 for final).
// ---------------------------------------------------------------------------
template<int NJTOT>
__global__ __launch_bounds__(256, 2) void stage_mma(const float* __restrict__ V,
                                                    const uint32_t* __restrict__ BhG,
                                                    float* __restrict__ OUT,
                                                    int cpair0)
{
    const int NB = NJTOT * 64;
    constexpr uint32_t PAN  = 1536u * 4u;     // bytes per panel
    constexpr uint32_t BUFB = 4u * PAN;       // A0 A1 B0 B1
    extern __shared__ uint32_t sm[];
    const uint32_t smb = smem_u32(sm);

    const int t    = threadIdx.x;
    const int lane = t & 31;
    const int wid  = t >> 5;
    const int wm   = wid >> 2;
    const int wn   = wid & 3;
    const int g    = lane >> 2;
    const int tg   = lane & 3;
    const int b0   = blockIdx.x * 128;
    const int nb0  = blockIdx.y * 128;

    const int row  = t >> 1;
    const int half = t & 1;

    const uint32_t* srcAh = g_phiH + (size_t)(b0 + row) * 1024 + cpair0 + half * 4;
    const uint32_t* srcBh = BhG + ((size_t)(nb0 + row)) * 8 + half * 4;
    const uint32_t dstA = smb + (row * 12 + half * 4) * 4;

    const int rr  = lane & 7;
    const int sub = lane >> 3;
    const uint32_t aoff = (uint32_t)(((wm * 64 + rr + ((sub & 1) << 3)) * 12 +
                                      ((sub >> 1) << 2)) * 4);
    const uint32_t boff = (uint32_t)(((wn * 32 + ((sub >> 1) << 3) + rr) * 12 +
                                      ((sub & 1) << 2)) * 4);

    float acc[4][4][4];
    #pragma unroll
    for (int a = 0; a < 4; a++)
        #pragma unroll
        for (int b = 0; b < 4; b++)
            #pragma unroll
            for (int c = 0; c < 4; c++) acc[a][b][c] = 0.f;

    // prologue: chunks 0,1,2
    #pragma unroll
    for (int c = 0; c < 3; c++) {
        uint32_t bb = (uint32_t)c * BUFB;
        #pragma unroll
        for (int p = 0; p < 2; p++) {
            CP_ASYNC16(dstA + bb + p * PAN,       srcAh + (2 * c + p) * 8);
            CP_ASYNC16(dstA + bb + (2 + p) * PAN, srcBh + (size_t)(2 * c + p) * NB * 8);
        }
        CP_COMMIT();
    }

    for (int c = 0; c < 16; c++) {
        if (c < 14)       CP_WAIT(2);
        else if (c == 14) CP_WAIT(1);
        else              CP_WAIT(0);
        __syncthreads();

        int cn = c + 3;
        if (cn < 16) {
            uint32_t bb = (uint32_t)(cn & 3) * BUFB;
            #pragma unroll
            for (int p = 0; p < 2; p++) {
                CP_ASYNC16(dstA + bb + p * PAN,       srcAh + (2 * cn + p) * 8);
                CP_ASYNC16(dstA + bb + (2 + p) * PAN, srcBh + (size_t)(2 * cn + p) * NB * 8);
            }
            CP_COMMIT();
        }

        const uint32_t base = smb + (uint32_t)(c & 3) * BUFB;
        #pragma unroll
        for (int p = 0; p < 2; p++) {
            uint32_t ah[4][4], bh[4][2];
            const uint32_t pa = base + (uint32_t)p * PAN;
            const uint32_t pb = base + 2u * PAN + (uint32_t)p * PAN;
            #pragma unroll
            for (int mf = 0; mf < 4; mf++)
                LDSM_X4(ah[mf][0], ah[mf][1], ah[mf][2], ah[mf][3], pa + aoff + mf * 768u);
            LDSM_X4(bh[0][0], bh[0][1], bh[1][0], bh[1][1], pb + boff);
            LDSM_X4(bh[2][0], bh[2][1], bh[3][0], bh[3][1], pb + boff + 768u);

            #pragma unroll
            for (int mf = 0; mf < 4; mf++)
                #pragma unroll
                for (int nf = 0; nf < 4; nf++)
                    mma_bf16(acc[mf][nf], ah[mf], bh[nf]);
        }
    }
    __syncthreads();

    // ---- epilogue: full i-fold in-block --------------------------------
    // col n = wn*32 + nf*8 + tg*2 + {0,1};  j = n>>6 (= wn>>1), i = n&63.
    const int jloc  = wn >> 1;               // 0..1
    const int ihalf = (wn & 1) * 32;         // i base for this warp
    float s[4][2];
    #pragma unroll
    for (int mf = 0; mf < 4; mf++) { s[mf][0] = 0.f; s[mf][1] = 0.f; }

    #pragma unroll
    for (int mf = 0; mf < 4; mf++) {
        int r = b0 + wm * 64 + mf * 16 + g;
        #pragma unroll
        for (int nf = 0; nf < 4; nf++) {
            int i = ihalf + nf * 8 + tg * 2;
            float2 v0 = *reinterpret_cast<const float2*>(V + (size_t)r * RNK + i);
            float2 v1 = *reinterpret_cast<const float2*>(V + (size_t)(r + 8) * RNK + i);
            s[mf][0] += acc[mf][nf][0] * v0.x + acc[mf][nf][1] * v0.y;
            s[mf][1] += acc[mf][nf][2] * v1.x + acc[mf][nf][3] * v1.y;
        }
    }
    // reduce across the 4 tg-lanes (lane bits 0-1)
    #pragma unroll
    for (int mf = 0; mf < 4; mf++) {
        #pragma unroll
        for (int k = 0; k < 2; k++) {
            s[mf][k] += __shfl_xor_sync(0xffffffffu, s[mf][k], 1);
            s[mf][k] += __shfl_xor_sync(0xffffffffu, s[mf][k], 2);
        }
    }

    float* sred = reinterpret_cast<float*>(sm);   // [128 rows][2 j][2 half]
    if (tg == 0) {
        #pragma unroll
        for (int mf = 0; mf < 4; mf++) {
            int r = wm * 64 + mf * 16 + g;
            sred[r * 4 + jloc * 2 + (wn & 1)]       = s[mf][0];
            sred[(r + 8) * 4 + jloc * 2 + (wn & 1)] = s[mf][1];
        }
    }
    __syncthreads();

    {   // 256 threads: row = t>>1, j = t&1
        int r = t >> 1, j = t & 1;
        float o = sred[r * 4 + j * 2] + sred[r * 4 + j * 2 + 1];
        OUT[(size_t)(b0 + r) * NJTOT + blockIdx.y * 2 + j] = o;
    }
}

// ---------------------------------------------------------------------------
// combine: dst[x] = sum_g part[g][x] (r0 split-K only), float4
// ---------------------------------------------------------------------------
__global__ void combine_kernel(float* __restrict__ dst, int ng, int nout)
{
    int n4 = BATCH * nout / 4;
    int x = blockIdx.x * blockDim.x + threadIdx.x;
    if (x < n4) {
        const float4* p = reinterpret_cast<const float4*>(g_part);
        float4 s = p[x];
        for (int g = 1; g < ng; g++) {
            float4 v = p[(size_t)g * n4 + x];
            s.x += v.x; s.y += v.y; s.z += v.z; s.w += v.w;
        }
        reinterpret_cast<float4*>(dst)[x] = s;
    }
}

// ---------------------------------------------------------------------------
extern "C" void kernel_launch(void* const* d_in, const int* in_sizes, int n_in,
                              void* d_out, int out_size)
{
    const float* X  = (const float*)d_in[0];
    const float* Cn = (const float*)d_in[1];
    const float* LS = (const float*)d_in[2];
    const float* G0 = (const float*)d_in[3];
    const float* G1 = (const float*)d_in[4];
    const float* G2 = (const float*)d_in[5];
    const float* G3 = (const float*)d_in[6];
    float* out = (float*)d_out;

    void *pR0, *pT1, *pT2, *pBh1, *pBh2, *pBh3;
    cudaGetSymbolAddress(&pR0, g_R0);
    cudaGetSymbolAddress(&pT1, g_t1);
    cudaGetSymbolAddress(&pT2, g_t2);
    cudaGetSymbolAddress(&pBh1, g_Bh1);
    cudaGetSymbolAddress(&pBh2, g_Bh2);
    cudaGetSymbolAddress(&pBh3, g_Bh3);

    const int smemStage = 4 * 6144 * 4;   // 98304 B (4 bufs x 24KB)
    static int s_init = 0;
    if (!s_init) {
        cudaFuncSetAttribute(stage_mma<64>, cudaFuncAttributeMaxDynamicSharedMemorySize, smemStage);
        cudaFuncSetAttribute(stage_mma<32>, cudaFuncAttributeMaxDynamicSharedMemorySize, smemStage);
        s_init = 1;
    }

    phi_kernel<<<dim3(2048 / 64, BATCH / 64), 256>>>(X, Cn, LS);
    packB_all<<<dim3(128, 32, 3), 256>>>(G1, G2, G3,
        (uint32_t*)pBh1, (uint32_t*)pBh2, (uint32_t*)pBh3);

    r0_kernel<<<dim3(BATCH / 64, 4), 256>>>(G0);
    combine_kernel<<<(BATCH * 64 / 4 + 255) / 256, 256>>>((float*)pR0, 4, 64);

    stage_mma<64><<<dim3(BATCH / 128, 32), 256, smemStage>>>(
        (const float*)pR0, (const uint32_t*)pBh1, (float*)pT1, 256);

    stage_mma<64><<<dim3(BATCH / 128, 32), 256, smemStage>>>(
        (const float*)pT1, (const uint32_t*)pBh2, (float*)pT2, 512);

    stage_mma<32><<<dim3(BATCH / 128, 16), 256, smemStage>>>(
        (const float*)pT2, (const uint32_t*)pBh3, out, 768);
}